// round 2
// baseline (speedup 1.0000x reference)
#include <cuda_runtime.h>
#include <math.h>

#define TT  8
#define NN  100000
#define HH  128
#define HIN 64
#define NODES_PER_CTA 32

// ---------------- device scratch (no allocations allowed) ----------------
__device__ float g_WT[3*HH*HH];      // combined qkv weights, [mat][c][j]: q[j] = sum_c A[c]*WT[c*H+j]
__device__ float g_bias[3*TT*HH];    // [mat][t][j] = (proj_b + pe[t]) @ w^T
__device__ float g_fcT[HH*HH];       // fcT[c][j] = fc_w[j][c]
__device__ float g_resT[HIN*HH];     // resT[c][j] = res_w[j][c]
__device__ float g_alpha[1];
__device__ float g_attn[(size_t)TT*NN*HH];   // 409.6 MB attention output scratch

// ---------------- kernel 0: fold proj into qkv, transpose weights ----------------
__global__ void prep_kernel(const float* __restrict__ proj_w, const float* __restrict__ proj_b,
                            const float* __restrict__ q_w, const float* __restrict__ k_w,
                            const float* __restrict__ v_w, const float* __restrict__ fc_w,
                            const float* __restrict__ res_w, const float* __restrict__ res_alpha)
{
    int idx = blockIdx.x * blockDim.x + threadIdx.x;
    const int NW = 3*HH*HH;                 // 49152
    const int NB = NW + 3*TT*HH;            // +3072
    const int NF = NB + HH*HH;              // +16384
    const int NR = NF + HIN*HH;             // +8192
    if (idx < NW) {
        int mat = idx / (HH*HH); int rem = idx % (HH*HH);
        int c = rem / HH, j = rem % HH;
        const float* w = (mat==0) ? q_w : ((mat==1) ? k_w : v_w);
        double s = 0.0;
        for (int m = 0; m < HH; m++) s += (double)w[j*HH+m] * (double)proj_w[m*HH+c];
        g_WT[idx] = (float)s;
    } else if (idx < NB) {
        int r = idx - NW;
        int mat = r / (TT*HH); int rr = r % (TT*HH);
        int t = rr / HH, j = rr % HH;
        const float* w = (mat==0) ? q_w : ((mat==1) ? k_w : v_w);
        double s = 0.0;
        for (int m = 0; m < HH; m++) {
            double div = exp((double)(m & ~1) * (-log(100000.0)) / (double)HH);
            double ph  = (double)(t + 1) * div;
            float pe   = (float)((m & 1) ? cos(ph) : sin(ph));   // numpy stores pe as f32
            s += ((double)proj_b[m] + (double)pe) * (double)w[j*HH+m];
        }
        g_bias[r] = (float)s;
    } else if (idx < NF) {
        int r = idx - NB;
        int c = r / HH, j = r % HH;
        g_fcT[r] = fc_w[j*HH + c];
    } else if (idx < NR) {
        int r = idx - NF;
        int c = r / HH, j = r % HH;
        g_resT[r] = res_w[j*HIN + c];
    } else if (idx == NR) {
        g_alpha[0] = 1.0f / (1.0f + expf(-res_alpha[0]));
    }
}

// ---------------- kernel 1: qkv + attention ----------------
// smem floats: WT 49152 | bias 3072 | A 1024 | qkv 3072 | S 64  => 56384 floats = 225536 B
#define K1_SMEM_BYTES (56384*4)

__global__ __launch_bounds__(256, 1) void attn_kernel(const float* __restrict__ inter)
{
    extern __shared__ float sm[];
    float* WT   = sm;
    float* bias = sm + 49152;
    float* As   = sm + 52224;
    float* qkv  = sm + 53248;
    float* S    = sm + 56320;

    int tid = threadIdx.x;
    int warp = tid >> 5, lane = tid & 31;

    for (int i = tid; i < 3*HH*HH; i += 256) WT[i] = g_WT[i];
    for (int i = tid; i < 3*TT*HH; i += 256) bias[i] = g_bias[i];

    for (int it = 0; it < NODES_PER_CTA; it++) {
        int n = blockIdx.x * NODES_PER_CTA + it;
        __syncthreads();   // prev iter fully consumed qkv/S; weights ready (iter 0)

        // phase 1: stage A[8][128] (warp w loads row t=w)
        {
            float4 v = *(const float4*)(inter + ((size_t)warp*NN + n)*HH + lane*4);
            *(float4*)(As + warp*HH + lane*4) = v;
        }
        __syncthreads();

        // phase 2: q,k,v = A @ WT + bias   (192 threads: mat x 2 t-halves x 32 j-quads)
        if (tid < 192) {
            int mat = tid / 64;
            int r   = tid & 63;
            int t0  = (r >> 5) * 4;
            int j0  = (r & 31) * 4;
            const float* W = WT + mat*HH*HH;
            const float* B = bias + mat*TT*HH;
            float acc[4][4];
            #pragma unroll
            for (int ti = 0; ti < 4; ti++)
                #pragma unroll
                for (int ji = 0; ji < 4; ji++)
                    acc[ti][ji] = B[(t0+ti)*HH + j0 + ji];
            #pragma unroll 4
            for (int c = 0; c < HH; c += 4) {
                float4 a[4];
                #pragma unroll
                for (int ti = 0; ti < 4; ti++) a[ti] = *(const float4*)(As + (t0+ti)*HH + c);
                #pragma unroll
                for (int ci = 0; ci < 4; ci++) {
                    float4 w = *(const float4*)(W + (c+ci)*HH + j0);
                    #pragma unroll
                    for (int ti = 0; ti < 4; ti++) {
                        float av = (&a[ti].x)[ci];
                        acc[ti][0] += av * w.x;
                        acc[ti][1] += av * w.y;
                        acc[ti][2] += av * w.z;
                        acc[ti][3] += av * w.w;
                    }
                }
            }
            float* dst = qkv + mat*TT*HH;
            #pragma unroll
            for (int ti = 0; ti < 4; ti++) {
                float4 o = { acc[ti][0], acc[ti][1], acc[ti][2], acc[ti][3] };
                *(float4*)(dst + (t0+ti)*HH + j0) = o;
            }
        }
        __syncthreads();

        // phase 3: scores row t=warp, softmax; phase 4: attn = S @ v
        {
            int t = warp;
            const float* q = qkv;
            const float* k = qkv + TT*HH;
            float qc[4];
            #pragma unroll
            for (int u = 0; u < 4; u++) qc[u] = q[t*HH + lane + 32*u];
            #pragma unroll
            for (int s = 0; s < TT; s++) {
                float p = 0.f;
                #pragma unroll
                for (int u = 0; u < 4; u++) p += qc[u] * k[s*HH + lane + 32*u];
                #pragma unroll
                for (int off = 16; off > 0; off >>= 1) p += __shfl_xor_sync(0xffffffffu, p, off);
                if (lane == 0) S[t*TT + s] = p;
            }
            __syncwarp();
            if (lane == 0) {
                float mx = S[t*TT];
                #pragma unroll
                for (int s = 1; s < TT; s++) mx = fmaxf(mx, S[t*TT + s]);
                float e[TT]; float sum = 0.f;
                #pragma unroll
                for (int s = 0; s < TT; s++) { e[s] = expf(S[t*TT + s] - mx); sum += e[s]; }
                float inv = 1.f / sum;
                #pragma unroll
                for (int s = 0; s < TT; s++) S[t*TT + s] = e[s] * inv;
            }
            __syncwarp();
            const float* v = qkv + 2*TT*HH;
            int j0 = lane * 4;
            float4 o = {0.f, 0.f, 0.f, 0.f};
            #pragma unroll
            for (int s = 0; s < TT; s++) {
                float sc = S[t*TT + s];
                float4 v4 = *(const float4*)(v + s*HH + j0);
                o.x += sc*v4.x; o.y += sc*v4.y; o.z += sc*v4.z; o.w += sc*v4.w;
            }
            *(float4*)(g_attn + ((size_t)t*NN + n)*HH + j0) = o;
        }
    }
}

// ---------------- kernel 2: fc + relu + gated residual + LayerNorm ----------------
// smem floats: fcT 16384 | resT 8192 | fcb 128 | resb 128 | lng 128 | lnb 128 | rowbuf 1024 | xbuf 512 | alpha 1 = 26625
#define K2_SMEM_BYTES (26625*4)

__global__ __launch_bounds__(256, 2) void out_kernel(const float* __restrict__ x,
        const float* __restrict__ fc_b, const float* __restrict__ res_b,
        const float* __restrict__ ln_g, const float* __restrict__ ln_b,
        float* __restrict__ out)
{
    extern __shared__ float sm[];
    float* fcT    = sm;
    float* resT   = sm + 16384;
    float* fcb    = sm + 24576;
    float* resb   = sm + 24704;
    float* lng    = sm + 24832;
    float* lnb    = sm + 24960;
    float* rowbuf = sm + 25088;   // 8 warps x 128
    float* xbuf   = sm + 26112;   // 8 warps x 64

    int tid = threadIdx.x;
    for (int i = tid; i < HH*HH;  i += 256) fcT[i]  = g_fcT[i];
    for (int i = tid; i < HIN*HH; i += 256) resT[i] = g_resT[i];
    if (tid < 128) { fcb[tid] = fc_b[tid]; resb[tid] = res_b[tid]; lng[tid] = ln_g[tid]; lnb[tid] = ln_b[tid]; }
    if (tid == 0) sm[26624] = g_alpha[0];
    __syncthreads();
    float alpha = sm[26624];
    float beta  = 1.f - alpha;

    int warp = tid >> 5, lane = tid & 31;
    int j0 = lane * 4;
    float* rb = rowbuf + warp*HH;
    float* xb = xbuf + warp*HIN;

    const long totalRows = (long)TT*NN;
    for (long row = (long)blockIdx.x*8 + warp; row < totalRows; row += (long)gridDim.x*8) {
        float4 a4 = *(const float4*)(g_attn + row*HH + j0);
        *(float4*)(rb + j0) = a4;
        if (lane < 16) {
            float4 xv = *(const float4*)(x + row*HIN + lane*4);
            *(float4*)(xb + lane*4) = xv;
        }
        __syncwarp();

        float acc[4];
        #pragma unroll
        for (int i = 0; i < 4; i++) acc[i] = fcb[j0 + i];
        #pragma unroll 4
        for (int c = 0; c < HH; c += 4) {
            float4 av = *(const float4*)(rb + c);
            #pragma unroll
            for (int ci = 0; ci < 4; ci++) {
                float4 w = *(const float4*)(fcT + (c+ci)*HH + j0);
                float a = (&av.x)[ci];
                acc[0] += a*w.x; acc[1] += a*w.y; acc[2] += a*w.z; acc[3] += a*w.w;
            }
        }
        float r[4];
        #pragma unroll
        for (int i = 0; i < 4; i++) r[i] = resb[j0 + i];
        #pragma unroll 4
        for (int c = 0; c < HIN; c += 4) {
            float4 xv = *(const float4*)(xb + c);
            #pragma unroll
            for (int ci = 0; ci < 4; ci++) {
                float4 w = *(const float4*)(resT + (c+ci)*HH + j0);
                float a = (&xv.x)[ci];
                r[0] += a*w.x; r[1] += a*w.y; r[2] += a*w.z; r[3] += a*w.w;
            }
        }
        float o[4]; float s = 0.f, s2 = 0.f;
        #pragma unroll
        for (int i = 0; i < 4; i++) {
            float h = fmaxf(acc[i], 0.f);
            o[i] = h*alpha + r[i]*beta;
            s  += o[i];
            s2 += o[i]*o[i];
        }
        #pragma unroll
        for (int off = 16; off > 0; off >>= 1) {
            s  += __shfl_xor_sync(0xffffffffu, s,  off);
            s2 += __shfl_xor_sync(0xffffffffu, s2, off);
        }
        float mean = s * (1.f/HH);
        float var  = s2 * (1.f/HH) - mean*mean;
        float inv  = rsqrtf(var + 1e-5f);
        float4 ov;
        #pragma unroll
        for (int i = 0; i < 4; i++) (&ov.x)[i] = (o[i] - mean)*inv*lng[j0+i] + lnb[j0+i];
        *(float4*)(out + row*HH + j0) = ov;
        __syncwarp();
    }
}

// ---------------- launch ----------------
extern "C" void kernel_launch(void* const* d_in, const int* in_sizes, int n_in,
                              void* d_out, int out_size)
{
    const float* inter     = (const float*)d_in[0];
    const float* x         = (const float*)d_in[1];
    const float* proj_w    = (const float*)d_in[2];
    const float* proj_b    = (const float*)d_in[3];
    const float* q_w       = (const float*)d_in[4];
    const float* k_w       = (const float*)d_in[5];
    const float* v_w       = (const float*)d_in[6];
    const float* fc_w      = (const float*)d_in[7];
    const float* fc_b      = (const float*)d_in[8];
    const float* res_w     = (const float*)d_in[9];
    const float* res_b     = (const float*)d_in[10];
    const float* res_alpha = (const float*)d_in[11];
    const float* ln_g      = (const float*)d_in[12];
    const float* ln_b      = (const float*)d_in[13];
    float* out = (float*)d_out;

    cudaFuncSetAttribute(attn_kernel, cudaFuncAttributeMaxDynamicSharedMemorySize, K1_SMEM_BYTES);
    cudaFuncSetAttribute(out_kernel,  cudaFuncAttributeMaxDynamicSharedMemorySize, K2_SMEM_BYTES);

    prep_kernel<<<301, 256>>>(proj_w, proj_b, q_w, k_w, v_w, fc_w, res_w, res_alpha);
    attn_kernel<<<NN / NODES_PER_CTA, 256, K1_SMEM_BYTES>>>(inter);
    out_kernel<<<2960, 256, K2_SMEM_BYTES>>>(x, fc_b, res_b, ln_g, ln_b, out);
}

// round 5
// speedup vs baseline: 3.2849x; 3.2849x over previous
#include <cuda_runtime.h>
#include <cuda_bf16.h>
#include <math.h>
#include <stdint.h>

#define TT  8
#define NN  100000
#define HH  128
#define HIN 64

// ---------------- device globals ----------------
__device__ float g_WB[384*HH];       // folded qkv weights [jg][c] (row-major, k contiguous)
__device__ float g_bias2[TT*384];    // [t][jg]
__device__ float g_pe[TT*HH];
__device__ float g_alpha[1];
__device__ float g_attn[(size_t)TT*NN*HH];

// ---------------- helpers ----------------
__device__ __forceinline__ void split_pack(float x, float y, uint32_t& hi, uint32_t& lo) {
    __nv_bfloat16 hx = __float2bfloat16(x);
    __nv_bfloat16 hy = __float2bfloat16(y);
    __nv_bfloat16 lx = __float2bfloat16(x - __bfloat162float(hx));
    __nv_bfloat16 ly = __float2bfloat16(y - __bfloat162float(hy));
    hi = ((uint32_t)__bfloat16_as_ushort(hy) << 16) | (uint32_t)__bfloat16_as_ushort(hx);
    lo = ((uint32_t)__bfloat16_as_ushort(ly) << 16) | (uint32_t)__bfloat16_as_ushort(lx);
}
__device__ __forceinline__ void mma16816(float* d, const uint32_t* a, const uint32_t* b) {
    asm volatile(
        "mma.sync.aligned.m16n8k16.row.col.f32.bf16.bf16.f32 "
        "{%0,%1,%2,%3}, {%4,%5,%6,%7}, {%8,%9}, {%0,%1,%2,%3};"
        : "+f"(d[0]), "+f"(d[1]), "+f"(d[2]), "+f"(d[3])
        : "r"(a[0]), "r"(a[1]), "r"(a[2]), "r"(a[3]), "r"(b[0]), "r"(b[1]));
}

// ---------------- prep1: PE + alpha ----------------
__global__ void prep1_kernel(const float* __restrict__ res_alpha) {
    int i = blockIdx.x * blockDim.x + threadIdx.x;
    if (i < TT*HH) {
        int t = i >> 7, m = i & 127;
        double div = exp((double)(m & ~1) * (-log(100000.0)) / 128.0);
        double phv = (double)(t + 1) * div;
        g_pe[i] = (float)((m & 1) ? cos(phv) : sin(phv));
    }
    if (i == 0) g_alpha[0] = 1.0f / (1.0f + expf(-res_alpha[0]));
}

// ---------------- prep2: fold proj into qkv (fp32) ----------------
__global__ void prep2_kernel(const float* __restrict__ proj_w, const float* __restrict__ proj_b,
                             const float* __restrict__ q_w, const float* __restrict__ k_w,
                             const float* __restrict__ v_w)
{
    int idx = blockIdx.x * blockDim.x + threadIdx.x;
    const int NW = 384*HH;
    const int NB = NW + TT*384;
    if (idx < NW) {
        int j = idx / HH, c = idx % HH;
        int mat = j >> 7, jj = j & 127;
        const float* w = (mat==0) ? q_w : ((mat==1) ? k_w : v_w);
        float s = 0.f;
        for (int m = 0; m < HH; m++) s += w[jj*HH+m] * proj_w[m*HH+c];
        g_WB[idx] = s;
    } else if (idx < NB) {
        int r = idx - NW;
        int t = r / 384, j = r % 384;
        int mat = j >> 7, jj = j & 127;
        const float* w = (mat==0) ? q_w : ((mat==1) ? k_w : v_w);
        float s = 0.f;
        for (int m = 0; m < HH; m++) s += (proj_b[m] + g_pe[t*HH+m]) * w[jj*HH+m];
        g_bias2[r] = s;
    }
}

// ---------------- attn kernel: HMMA qkv + shuffle attention ----------------
// M=32 tile (4 nodes). smem: Blo 384*68*4=104448 | Ahi 32*68*4=8704 | Alo 8704
//                            C 32*388*4=49664 | bias 12288  => 183808
#define SA_BLO   0
#define SA_AHI   104448
#define SA_ALO   113152
#define SA_C     121856
#define SA_BIAS  171520
#define SA_TOTAL 183808
#define CST      388

__global__ __launch_bounds__(256, 1) void attn_mma_kernel(const float* __restrict__ inter)
{
    extern __shared__ char smc[];
    uint32_t* Blo = (uint32_t*)(smc + SA_BLO);   // [384][68] packed bf16-lo pairs
    uint32_t* Ahi = (uint32_t*)(smc + SA_AHI);   // [32][68]
    uint32_t* Alo = (uint32_t*)(smc + SA_ALO);
    float*    C   = (float*)(smc + SA_C);        // [32][388]
    float*  sbias = (float*)(smc + SA_BIAS);     // [8][384]

    int tid = threadIdx.x, warp = tid >> 5, lane = tid & 31;
    int g = lane >> 2, tc = lane & 3;
    int n0 = warp * 48;

    // stage B-lo + bias (once)
    for (int i = tid; i < 384*64; i += 256) {
        int n = i >> 6, cp = i & 63;
        float2 w = *(const float2*)(g_WB + n*128 + cp*2);
        uint32_t h, l; split_pack(w.x, w.y, h, l);
        Blo[n*68 + cp] = l;
    }
    for (int i = tid; i < TT*384; i += 256) sbias[i] = g_bias2[i];

    // per-warp B-hi fragments in registers (once)
    uint32_t bh[6][8][2];
    #pragma unroll
    for (int nn = 0; nn < 6; nn++) {
        #pragma unroll
        for (int kk = 0; kk < 8; kk++) {
            int n = n0 + nn*8 + g;
            int k = kk*16 + tc*2;
            float2 w0 = *(const float2*)(g_WB + n*128 + k);
            float2 w1 = *(const float2*)(g_WB + n*128 + k + 8);
            uint32_t h, l;
            split_pack(w0.x, w0.y, h, l); bh[nn][kk][0] = h;
            split_pack(w1.x, w1.y, h, l); bh[nn][kk][1] = h;
        }
    }
    __syncthreads();

    for (int tile = blockIdx.x; tile < NN/4; tile += gridDim.x) {
        // ---- stage A (32 rows x 128 cols), packed hi/lo ----
        for (int i = tid; i < 2048; i += 256) {
            int row = i >> 6, cp = i & 63;
            int t = row & 7, nl = row >> 3;
            float2 a = *(const float2*)(inter + ((size_t)t*NN + (size_t)(tile*4 + nl))*HH + cp*2);
            uint32_t h, l; split_pack(a.x, a.y, h, l);
            Ahi[row*68 + cp] = h;
            Alo[row*68 + cp] = l;
        }
        __syncthreads();

        // ---- MMA: C[32][384] = A x W, 3 precision passes ----
        #pragma unroll
        for (int mm = 0; mm < 2; mm++) {
            float acc[6][4];
            #pragma unroll
            for (int nn = 0; nn < 6; nn++) {
                acc[nn][0] = 0.f; acc[nn][1] = 0.f; acc[nn][2] = 0.f; acc[nn][3] = 0.f;
            }
            #pragma unroll
            for (int kh = 0; kh < 2; kh++) {
                uint32_t ah[4][4], al[4][4];
                #pragma unroll
                for (int q = 0; q < 4; q++) {
                    int kk = kh*4 + q;
                    int base = (mm*16 + g)*68 + kk*8 + tc;
                    ah[q][0] = Ahi[base];          al[q][0] = Alo[base];
                    ah[q][1] = Ahi[base + 8*68];   al[q][1] = Alo[base + 8*68];
                    ah[q][2] = Ahi[base + 4];      al[q][2] = Alo[base + 4];
                    ah[q][3] = Ahi[base + 8*68+4]; al[q][3] = Alo[base + 8*68+4];
                }
                #pragma unroll
                for (int nn = 0; nn < 6; nn++) {
                    #pragma unroll
                    for (int q = 0; q < 4; q++) {
                        int kk = kh*4 + q;
                        int bb = (n0 + nn*8 + g)*68 + kk*8 + tc;
                        uint32_t bl[2] = { Blo[bb], Blo[bb + 4] };
                        mma16816(acc[nn], ah[q], bh[nn][kk]);
                        mma16816(acc[nn], ah[q], bl);
                        mma16816(acc[nn], al[q], bh[nn][kk]);
                    }
                }
            }
            // write C with bias (row & 7 == g for both halves)
            #pragma unroll
            for (int nn = 0; nn < 6; nn++) {
                int j = n0 + nn*8 + tc*2;
                float2 b = *(const float2*)(sbias + g*384 + j);
                int rlo = mm*16 + g, rhi = rlo + 8;
                *(float2*)(C + rlo*CST + j) = make_float2(acc[nn][0]+b.x, acc[nn][1]+b.y);
                *(float2*)(C + rhi*CST + j) = make_float2(acc[nn][2]+b.x, acc[nn][3]+b.y);
            }
        }
        __syncthreads();

        // ---- attention epilogue: 32 (node,t) tasks over 8 warps ----
        for (int task = warp; task < 32; task += 8) {
            int nl = task >> 3, t = task & 7;
            const float* Cb = C + nl*8*CST;
            float qv[4];
            #pragma unroll
            for (int u = 0; u < 4; u++) qv[u] = Cb[t*CST + lane + 32*u];
            float sc[8];
            #pragma unroll
            for (int s = 0; s < 8; s++) {
                float p = 0.f;
                #pragma unroll
                for (int u = 0; u < 4; u++) p += qv[u] * Cb[s*CST + 128 + lane + 32*u];
                #pragma unroll
                for (int o = 16; o > 0; o >>= 1) p += __shfl_xor_sync(0xffffffffu, p, o);
                sc[s] = p;
            }
            float mx = sc[0];
            #pragma unroll
            for (int s = 1; s < 8; s++) mx = fmaxf(mx, sc[s]);
            float sum = 0.f;
            #pragma unroll
            for (int s = 0; s < 8; s++) { sc[s] = expf(sc[s] - mx); sum += sc[s]; }
            float inv = 1.f / sum;
            float of[4] = {0.f, 0.f, 0.f, 0.f};
            #pragma unroll
            for (int s = 0; s < 8; s++) {
                float w = sc[s] * inv;
                #pragma unroll
                for (int u = 0; u < 4; u++) of[u] += w * Cb[s*CST + 256 + lane + 32*u];
            }
            size_t node = (size_t)(tile*4 + nl);
            #pragma unroll
            for (int u = 0; u < 4; u++)
                g_attn[((size_t)t*NN + node)*HH + lane + 32*u] = of[u];
        }
        __syncthreads();
    }
}

// ---------------- out kernel: HMMA fc+res + gate + LayerNorm ----------------
// smem: fcBlo 34816 | resBlo 18432 | Ahi 17408 | Alo 17408 | Xhi 9216 | Xlo 9216 | C 33792 | par 2064
#define SO_FCBLO  0
#define SO_RESBLO 34816
#define SO_AHI    53248
#define SO_ALO    70656
#define SO_XHI    88064
#define SO_XLO    97280
#define SO_C      106496
#define SO_PAR    140288
#define SO_TOTAL  142352

__global__ __launch_bounds__(256, 1) void out_mma_kernel(const float* __restrict__ x,
        const float* __restrict__ fc_w, const float* __restrict__ fc_b,
        const float* __restrict__ res_w, const float* __restrict__ res_b,
        const float* __restrict__ ln_g, const float* __restrict__ ln_b,
        float* __restrict__ out)
{
    extern __shared__ char smc[];
    uint32_t* fBlo = (uint32_t*)(smc + SO_FCBLO);   // [128][68]
    uint32_t* rBlo = (uint32_t*)(smc + SO_RESBLO);  // [128][36]
    uint32_t* Ahi  = (uint32_t*)(smc + SO_AHI);     // [64][68]
    uint32_t* Alo  = (uint32_t*)(smc + SO_ALO);
    uint32_t* Xhi  = (uint32_t*)(smc + SO_XHI);     // [64][36]
    uint32_t* Xlo  = (uint32_t*)(smc + SO_XLO);
    float*    C    = (float*)(smc + SO_C);          // [64][132]
    float*    par  = (float*)(smc + SO_PAR);

    int tid = threadIdx.x, warp = tid >> 5, lane = tid & 31;
    int g = lane >> 2, tc = lane & 3;
    int n0 = warp * 16;

    for (int i = tid; i < 128*64; i += 256) {
        int n = i >> 6, cp = i & 63;
        float2 w = *(const float2*)(fc_w + n*128 + cp*2);
        uint32_t h, l; split_pack(w.x, w.y, h, l);
        fBlo[n*68 + cp] = l;
    }
    for (int i = tid; i < 128*32; i += 256) {
        int n = i >> 5, cp = i & 31;
        float2 w = *(const float2*)(res_w + n*64 + cp*2);
        uint32_t h, l; split_pack(w.x, w.y, h, l);
        rBlo[n*36 + cp] = l;
    }
    if (tid < 128) {
        par[tid] = fc_b[tid]; par[128+tid] = res_b[tid];
        par[256+tid] = ln_g[tid]; par[384+tid] = ln_b[tid];
    }
    if (tid == 0) par[512] = g_alpha[0];

    uint32_t bf[2][8][2], br[2][4][2];
    #pragma unroll
    for (int nn = 0; nn < 2; nn++) {
        int n = n0 + nn*8 + g;
        #pragma unroll
        for (int kk = 0; kk < 8; kk++) {
            int k = kk*16 + tc*2;
            float2 w0 = *(const float2*)(fc_w + n*128 + k);
            float2 w1 = *(const float2*)(fc_w + n*128 + k + 8);
            uint32_t h, l;
            split_pack(w0.x, w0.y, h, l); bf[nn][kk][0] = h;
            split_pack(w1.x, w1.y, h, l); bf[nn][kk][1] = h;
        }
        #pragma unroll
        for (int kk = 0; kk < 4; kk++) {
            int k = kk*16 + tc*2;
            float2 w0 = *(const float2*)(res_w + n*64 + k);
            float2 w1 = *(const float2*)(res_w + n*64 + k + 8);
            uint32_t h, l;
            split_pack(w0.x, w0.y, h, l); br[nn][kk][0] = h;
            split_pack(w1.x, w1.y, h, l); br[nn][kk][1] = h;
        }
    }
    __syncthreads();
    float alpha = par[512];
    float beta  = 1.f - alpha;

    const int nTiles = (TT*NN)/64;   // 12500
    for (int tile = blockIdx.x; tile < nTiles; tile += gridDim.x) {
        size_t r0 = (size_t)tile * 64;
        for (int i = tid; i < 4096; i += 256) {
            int row = i >> 6, cp = i & 63;
            float2 a = *(const float2*)(g_attn + (r0 + row)*HH + cp*2);
            uint32_t h, l; split_pack(a.x, a.y, h, l);
            Ahi[row*68 + cp] = h; Alo[row*68 + cp] = l;
        }
        for (int i = tid; i < 2048; i += 256) {
            int row = i >> 5, cp = i & 31;
            float2 a = *(const float2*)(x + (r0 + row)*HIN + cp*2);
            uint32_t h, l; split_pack(a.x, a.y, h, l);
            Xhi[row*36 + cp] = h; Xlo[row*36 + cp] = l;
        }
        __syncthreads();

        #pragma unroll
        for (int mm = 0; mm < 4; mm++) {
            float accf[2][4];
            #pragma unroll
            for (int nn = 0; nn < 2; nn++) { accf[nn][0]=0.f; accf[nn][1]=0.f; accf[nn][2]=0.f; accf[nn][3]=0.f; }
            #pragma unroll
            for (int kh = 0; kh < 2; kh++) {
                uint32_t ah[4][4], al[4][4];
                #pragma unroll
                for (int q = 0; q < 4; q++) {
                    int kk = kh*4 + q;
                    int base = (mm*16 + g)*68 + kk*8 + tc;
                    ah[q][0] = Ahi[base];          al[q][0] = Alo[base];
                    ah[q][1] = Ahi[base + 8*68];   al[q][1] = Alo[base + 8*68];
                    ah[q][2] = Ahi[base + 4];      al[q][2] = Alo[base + 4];
                    ah[q][3] = Ahi[base + 8*68+4]; al[q][3] = Alo[base + 8*68+4];
                }
                #pragma unroll
                for (int nn = 0; nn < 2; nn++) {
                    #pragma unroll
                    for (int q = 0; q < 4; q++) {
                        int kk = kh*4 + q;
                        int bb = (n0 + nn*8 + g)*68 + kk*8 + tc;
                        uint32_t bl[2] = { fBlo[bb], fBlo[bb + 4] };
                        mma16816(accf[nn], ah[q], bf[nn][kk]);
                        mma16816(accf[nn], ah[q], bl);
                        mma16816(accf[nn], al[q], bf[nn][kk]);
                    }
                }
            }
            float accr[2][4];
            #pragma unroll
            for (int nn = 0; nn < 2; nn++) { accr[nn][0]=0.f; accr[nn][1]=0.f; accr[nn][2]=0.f; accr[nn][3]=0.f; }
            {
                uint32_t ah[4][4], al[4][4];
                #pragma unroll
                for (int kk = 0; kk < 4; kk++) {
                    int base = (mm*16 + g)*36 + kk*8 + tc;
                    ah[kk][0] = Xhi[base];          al[kk][0] = Xlo[base];
                    ah[kk][1] = Xhi[base + 8*36];   al[kk][1] = Xlo[base + 8*36];
                    ah[kk][2] = Xhi[base + 4];      al[kk][2] = Xlo[base + 4];
                    ah[kk][3] = Xhi[base + 8*36+4]; al[kk][3] = Xlo[base + 8*36+4];
                }
                #pragma unroll
                for (int nn = 0; nn < 2; nn++) {
                    #pragma unroll
                    for (int kk = 0; kk < 4; kk++) {
                        int bb = (n0 + nn*8 + g)*36 + kk*8 + tc;
                        uint32_t bl[2] = { rBlo[bb], rBlo[bb + 4] };
                        mma16816(accr[nn], ah[kk], br[nn][kk]);
                        mma16816(accr[nn], ah[kk], bl);
                        mma16816(accr[nn], al[kk], br[nn][kk]);
                    }
                }
            }
            #pragma unroll
            for (int nn = 0; nn < 2; nn++) {
                int j = n0 + nn*8 + tc*2;
                float2 fb = *(const float2*)(par + j);
                float2 rb = *(const float2*)(par + 128 + j);
                int rlo = mm*16 + g, rhi = rlo + 8;
                float v0 = fmaxf(accf[nn][0]+fb.x, 0.f)*alpha + (accr[nn][0]+rb.x)*beta;
                float v1 = fmaxf(accf[nn][1]+fb.y, 0.f)*alpha + (accr[nn][1]+rb.y)*beta;
                float v2 = fmaxf(accf[nn][2]+fb.x, 0.f)*alpha + (accr[nn][2]+rb.x)*beta;
                float v3 = fmaxf(accf[nn][3]+fb.y, 0.f)*alpha + (accr[nn][3]+rb.y)*beta;
                *(float2*)(C + rlo*132 + j) = make_float2(v0, v1);
                *(float2*)(C + rhi*132 + j) = make_float2(v2, v3);
            }
        }
        __syncthreads();

        #pragma unroll
        for (int r8 = 0; r8 < 8; r8++) {
            int r = warp*8 + r8;
            float o[4];
            float s = 0.f, s2 = 0.f;
            #pragma unroll
            for (int u = 0; u < 4; u++) {
                o[u] = C[r*132 + lane + 32*u];
                s += o[u]; s2 += o[u]*o[u];
            }
            #pragma unroll
            for (int off = 16; off > 0; off >>= 1) {
                s  += __shfl_xor_sync(0xffffffffu, s,  off);
                s2 += __shfl_xor_sync(0xffffffffu, s2, off);
            }
            float mean = s * (1.f/HH);
            float var  = s2 * (1.f/HH) - mean*mean;
            float inv  = rsqrtf(var + 1e-5f);
            #pragma unroll
            for (int u = 0; u < 4; u++) {
                int col = lane + 32*u;
                out[(r0 + r)*HH + col] = (o[u]-mean)*inv*par[256+col] + par[384+col];
            }
        }
        __syncthreads();
    }
}

// ---------------- launch ----------------
extern "C" void kernel_launch(void* const* d_in, const int* in_sizes, int n_in,
                              void* d_out, int out_size)
{
    const float* inter     = (const float*)d_in[0];
    const float* x         = (const float*)d_in[1];
    const float* proj_w    = (const float*)d_in[2];
    const float* proj_b    = (const float*)d_in[3];
    const float* q_w       = (const float*)d_in[4];
    const float* k_w       = (const float*)d_in[5];
    const float* v_w       = (const float*)d_in[6];
    const float* fc_w      = (const float*)d_in[7];
    const float* fc_b      = (const float*)d_in[8];
    const float* res_w     = (const float*)d_in[9];
    const float* res_b     = (const float*)d_in[10];
    const float* res_alpha = (const float*)d_in[11];
    const float* ln_g      = (const float*)d_in[12];
    const float* ln_b      = (const float*)d_in[13];
    float* out = (float*)d_out;

    cudaFuncSetAttribute(attn_mma_kernel, cudaFuncAttributeMaxDynamicSharedMemorySize, SA_TOTAL);
    cudaFuncSetAttribute(out_mma_kernel,  cudaFuncAttributeMaxDynamicSharedMemorySize, SO_TOTAL);

    prep1_kernel<<<4, 256>>>(res_alpha);
    prep2_kernel<<<205, 256>>>(proj_w, proj_b, q_w, k_w, v_w);
    attn_mma_kernel<<<148, 256, SA_TOTAL>>>(inter);
    out_mma_kernel<<<148, 256, SO_TOTAL>>>(x, fc_w, fc_b, res_w, res_b, ln_g, ln_b, out);
}